// round 15
// baseline (speedup 1.0000x reference)
#include <cuda_runtime.h>
#include <cstdint>
#include <math.h>

// Problem dims
#define BB 64
#define TT 4096
#define HH 256
#define II 7
#define XD 12   // I + F

#define NRNN 64
#define NWORK 84
#define NCTA (NRNN + NWORK)
#define NT2 256

// ---------------- device scratch ----------------------------------------------
__device__ float g_ht[(size_t)BB * TT * HH];   // RNN hidden states (256 MB)
__device__ float g_xw[(size_t)BB * TT * HH];   // precomputed xW + biases (256 MB)
__device__ float g_wt[110520];                 // transposed MLP weights
__device__ int   g_prog[BB];                   // RNN progress per chain
__device__ int   g_tick;                       // MLP chunk ticket counter

// MLP layer offsets in g_wt
#define OFF0 0
#define OFF1 66816
#define OFF2 99584
#define OFF3 107776
#define OFF4 109824
#define OFF5 110336
#define OFF6 110464

// ---------------- helpers ------------------------------------------------------
__device__ __forceinline__ unsigned long long fma2(unsigned long long a,
                                                   unsigned long long b,
                                                   unsigned long long c) {
    unsigned long long d;
    asm("fma.rn.f32x2 %0, %1, %2, %3;" : "=l"(d) : "l"(a), "l"(b), "l"(c));
    return d;
}
__device__ __forceinline__ unsigned long long pack2(float lo, float hi) {
    unsigned long long d;
    asm("mov.b64 %0, {%1, %2};" : "=l"(d) : "f"(lo), "f"(hi));
    return d;
}
__device__ __forceinline__ float2 unpack2(unsigned long long v) {
    float lo, hi;
    asm("mov.b64 {%0, %1}, %2;" : "=f"(lo), "=f"(hi) : "l"(v));
    return make_float2(lo, hi);
}
__device__ __forceinline__ int ld_acquire(const int* p) {
    int v;
    asm volatile("ld.global.acquire.gpu.b32 %0, [%1];" : "=r"(v) : "l"(p));
    return v;
}
__device__ __forceinline__ void st_release(int* p, int v) {
    asm volatile("st.global.release.gpu.b32 [%0], %1;" :: "l"(p), "r"(v));
}
__device__ __forceinline__ float fast_tanh(float x) {
    float e = __expf(2.0f * x);
    return 1.0f - __fdividef(2.0f, e + 1.0f);
}
// tanh given PRE-DOUBLED argument x2 = 2x: tanh = 1 - 2/(exp(x2)+1)
__device__ __forceinline__ float fast_tanh2(float x2) {
    float e;
    asm("{ .reg .f32 t; mul.f32 t, %1, 0f3FB8AA3B; ex2.approx.f32 %0, t; }"
        : "=f"(e) : "f"(x2));                       // e = 2^(x2*log2e) = exp(x2)
    float r;
    asm("{ .reg .f32 t; add.f32 t, %1, 0f3F800000; rcp.approx.f32 %0, t; }"
        : "=f"(r) : "f"(e));                        // r = 1/(e+1)
    return fmaf(-2.0f, r, 1.0f);
}
__device__ __forceinline__ void cpa16(uint32_t s, const void* g) {
    asm volatile("cp.async.cg.shared.global [%0], [%1], 16;" :: "r"(s), "l"(g));
}
__device__ __forceinline__ void cpa_commit() {
    asm volatile("cp.async.commit_group;" ::: "memory");
}

// ---------------- RNN config ---------------------------------------------------
// 256 threads, one CTA per chain. warp w = tid>>5; lane: g = lane>>2 (k-group of
// 32 k), rr = lane&3. Thread: rows j0..j0+7 (j0 = w*32 + rr*8), k in [g*32,+32).
// Per row: 26 weight floats (13 ull, pairs 0..12) in regs, 6 (pairs 13..15) smem.
#define RKU 13        // reg ulls per row
#define WROW 8        // smem weight row stride (pair13 @0, pairs14-15 @4)
#define WTST 68       // per-thread smem weight stride (64 used + 4 pad)
#define HPAD 36       // h group stride (32 used + 4 pad) -> conflict-free
#define HBUF 288      // h buffer stride (8*HPAD)
#define CH 32         // xw chunk (steps)
#define NCH (TT / CH) // 128

#define RNN_SMF (NT2 * WTST + 2 * CH * HH + 2 * HBUF)

// ---------------- MLP config ---------------------------------------------------
#define TOKN 64
#define TOKP 68
#define MLP_SMF ((264 + 256) * TOKP)                   // 35360 fl = 141440 B
#define FUSED_SMEM_B (MLP_SMF * 4)

template<int DOUT, int DIN, int TPG, bool LEAKY>
__device__ __forceinline__ void mlp_layer(const float* __restrict__ zin,
                                          float* __restrict__ zout,
                                          const float* __restrict__ wt,
                                          const float* __restrict__ bias)
{
    const int tid = threadIdx.x;
    const int o = tid % DOUT;
    const int g = tid / DOUT;

    if constexpr (TPG >= 4) {
        constexpr int NP = TPG / 2;
        unsigned long long acc[NP];
        #pragma unroll
        for (int p = 0; p < NP; p++) acc[p] = pack2(0.0f, 0.0f);
        #pragma unroll 4
        for (int k = 0; k < DIN; k++) {
            const float w = wt[k * DOUT + o];
            const unsigned long long w2 = pack2(w, w);
            const ulonglong2* zr = (const ulonglong2*)(zin + k * TOKP + g * TPG);
            #pragma unroll
            for (int p = 0; p < TPG / 4; p++) {
                ulonglong2 u = zr[p];
                acc[2 * p]     = fma2(w2, u.x, acc[2 * p]);
                acc[2 * p + 1] = fma2(w2, u.y, acc[2 * p + 1]);
            }
        }
        const float bv = bias[o];
        float* orow = zout + o * TOKP + g * TPG;
        #pragma unroll
        for (int p = 0; p < NP; p++) {
            float2 v = unpack2(acc[p]);
            v.x += bv; v.y += bv;
            if (LEAKY) { v.x = fmaxf(v.x, 0.01f * v.x); v.y = fmaxf(v.y, 0.01f * v.y); }
            orow[2 * p] = v.x; orow[2 * p + 1] = v.y;
        }
    } else if constexpr (TPG == 2) {
        unsigned long long acc = pack2(0.0f, 0.0f);
        #pragma unroll 4
        for (int k = 0; k < DIN; k++) {
            const float w = wt[k * DOUT + o];
            unsigned long long u = *(const unsigned long long*)(zin + k * TOKP + g * 2);
            acc = fma2(pack2(w, w), u, acc);
        }
        const float bv = bias[o];
        float2 v = unpack2(acc);
        v.x += bv; v.y += bv;
        if (LEAKY) { v.x = fmaxf(v.x, 0.01f * v.x); v.y = fmaxf(v.y, 0.01f * v.y); }
        float* orow = zout + o * TOKP + g * 2;
        orow[0] = v.x; orow[1] = v.y;
    }
}

// ---------------- RNN side ------------------------------------------------------
__device__ void rnn_cta(const float* __restrict__ W_hh, float* __restrict__ out,
                        float* sm, int b)
{
    float* ws  = sm;                         // NT2*WTST
    float* xws = sm + NT2 * WTST;            // 2 x CH*HH
    float* hb  = xws + 2 * CH * HH;          // 2*HBUF
    const int tid = threadIdx.x;
    const int w = tid >> 5, lane = tid & 31;
    const int g = lane >> 2, rr = lane & 3;
    const int j0 = w * 32 + rr * 8;
    const int myrow = j0 + g;
    const int hoff = HPAD * (myrow >> 5) + (myrow & 31);
    const bool g0b = (g & 1) != 0;
    const bool g1b = (g & 2) != 0;
    const bool g2b = (g & 4) != 0;

    // register weights: 8 rows x 26 k (13 ull each, pairs 0..12)
    unsigned long long wr[8][RKU];
    #pragma unroll
    for (int r = 0; r < 8; r++) {
        const float* row = W_hh + (j0 + r) * HH + g * 32;
        const ulonglong2* src = (const ulonglong2*)row;
        #pragma unroll
        for (int i = 0; i < 6; i++) {
            ulonglong2 u = src[i];
            wr[r][2 * i] = u.x; wr[r][2 * i + 1] = u.y;
        }
        wr[r][12] = *(const unsigned long long*)(row + 24);
    }
    // smem weights: 8 rows x 6 k (pair 13 @0 as 8B, pairs 14-15 @4 as 16B)
    float* wsm = ws + tid * WTST;
    #pragma unroll
    for (int r = 0; r < 8; r++) {
        const float* row = W_hh + (j0 + r) * HH + g * 32;
        *(unsigned long long*)(wsm + r * WROW) =
            *(const unsigned long long*)(row + 26);
        *(ulonglong2*)(wsm + r * WROW + 4) =
            *(const ulonglong2*)(row + 28);
    }

    for (int idx = tid; idx < 2 * HBUF; idx += NT2) hb[idx] = 0.0f;

    const float* xg = g_xw + (size_t)b * TT * HH;
    float* hout = g_ht + (size_t)b * TT * HH;
    const uint32_t xw_sbase = (uint32_t)__cvta_generic_to_shared(xws);

    // prologue: stage chunks 0 and 1 (CH*HH = 8192 fl = 2048 float4)
    #pragma unroll
    for (int i = 0; i < 8; i++)
        cpa16(xw_sbase + (uint32_t)(tid + i * NT2) * 16,
              (const float4*)xg + tid + i * NT2);
    cpa_commit();
    #pragma unroll
    for (int i = 0; i < 8; i++)
        cpa16(xw_sbase + (uint32_t)(CH * HH / 4 + tid + i * NT2) * 16,
              (const float4*)(xg + CH * HH) + tid + i * NT2);
    cpa_commit();

    int buf = 0;
    float hl = 0.0f;
    float xw2 = 0.0f;         // pre-doubled xw for current step
    bool xw2_valid = false;

    for (int c = 0; c < NCH; c++) {
        if (c >= NCH - 2) { asm volatile("cp.async.wait_group 0;" ::: "memory"); }
        else              { asm volatile("cp.async.wait_group 1;" ::: "memory"); }
        __syncthreads();
        const float* xwc = xws + (c & 1) * (CH * HH);
        if (!xw2_valid) { xw2 = 2.0f * xwc[myrow]; xw2_valid = true; }

        for (int s = 0; s < CH; s++) {
            const ulonglong2* h2 = (const ulonglong2*)(hb + buf * HBUF + HPAD * g);

            // ---- issue all smem loads first (overlap with reg-FMA block) ----
            ulonglong2 u6 = h2[6];
            ulonglong2 u7 = h2[7];
            unsigned long long w13[8];
            ulonglong2 w45[8];
            #pragma unroll
            for (int r = 0; r < 8; r++) {
                w13[r] = *(const unsigned long long*)(wsm + r * WROW);
                w45[r] = *(const ulonglong2*)(wsm + r * WROW + 4);
            }

            unsigned long long acc[8];
            #pragma unroll
            for (int r = 0; r < 8; r++) acc[r] = pack2(0.f, 0.f);

            // pairs 0..11: register weights
            #pragma unroll
            for (int i = 0; i < 6; i++) {
                ulonglong2 u = h2[i];
                #pragma unroll
                for (int r = 0; r < 8; r++) {
                    acc[r] = fma2(wr[r][2 * i],     u.x, acc[r]);
                    acc[r] = fma2(wr[r][2 * i + 1], u.y, acc[r]);
                }
            }
            // pair 12 (reg) + pair 13 (smem)
            #pragma unroll
            for (int r = 0; r < 8; r++)
                acc[r] = fma2(wr[r][12], u6.x, acc[r]);
            #pragma unroll
            for (int r = 0; r < 8; r++)
                acc[r] = fma2(w13[r], u6.y, acc[r]);
            // pairs 14,15 (smem)
            #pragma unroll
            for (int r = 0; r < 8; r++) {
                acc[r] = fma2(w45[r].x, u7.x, acc[r]);
                acc[r] = fma2(w45[r].y, u7.y, acc[r]);
            }

            float p0, p1, p2, p3, p4, p5, p6, p7;
            { float2 v = unpack2(acc[0]); p0 = v.x + v.y; }
            { float2 v = unpack2(acc[1]); p1 = v.x + v.y; }
            { float2 v = unpack2(acc[2]); p2 = v.x + v.y; }
            { float2 v = unpack2(acc[3]); p3 = v.x + v.y; }
            { float2 v = unpack2(acc[4]); p4 = v.x + v.y; }
            { float2 v = unpack2(acc[5]); p5 = v.x + v.y; }
            { float2 v = unpack2(acc[6]); p6 = v.x + v.y; }
            { float2 v = unpack2(acc[7]); p7 = v.x + v.y; }

            // 3-stage reduce-scatter: lane (rr,g) ends with row j0+g.
            float q0, q1, q2, q3;
            {
                float o0 = __shfl_xor_sync(0xFFFFFFFFu, g0b ? p0 : p1, 4);
                q0 = (g0b ? p1 : p0) + o0;
                float o1 = __shfl_xor_sync(0xFFFFFFFFu, g0b ? p2 : p3, 4);
                q1 = (g0b ? p3 : p2) + o1;
                float o2 = __shfl_xor_sync(0xFFFFFFFFu, g0b ? p4 : p5, 4);
                q2 = (g0b ? p5 : p4) + o2;
                float o3 = __shfl_xor_sync(0xFFFFFFFFu, g0b ? p6 : p7, 4);
                q3 = (g0b ? p7 : p6) + o3;
            }
            float u0, u1;
            {
                float o0 = __shfl_xor_sync(0xFFFFFFFFu, g1b ? q0 : q1, 8);
                u0 = (g1b ? q1 : q0) + o0;
                float o1 = __shfl_xor_sync(0xFFFFFFFFu, g1b ? q2 : q3, 8);
                u1 = (g1b ? q3 : q2) + o1;
            }
            float sd;
            {
                float o = __shfl_xor_sync(0xFFFFFFFFu, g2b ? u0 : u1, 16);
                sd = (g2b ? u1 : u0) + o;
            }

            const float hn = fast_tanh2(fmaf(2.0f, sd, xw2));
            hb[(buf ^ 1) * HBUF + hoff] = hn;
            hout[(size_t)(c * CH + s) * HH + myrow] = hn;
            hl = hn;
            // prefetch next step's pre-doubled xw (same chunk only)
            if (s + 1 < CH) xw2 = 2.0f * xwc[(s + 1) * HH + myrow];
            else xw2_valid = false;
            __syncthreads();
            buf ^= 1;
        }

        if (tid == 0) st_release(&g_prog[b], (c + 1) * CH);

        if (c + 2 < NCH) {
            const float4* gb = (const float4*)(xg + (size_t)(c + 2) * CH * HH);
            const uint32_t sb = xw_sbase + (uint32_t)((c & 1) * CH * HH) * 4;
            #pragma unroll
            for (int i = 0; i < 8; i++)
                cpa16(sb + (uint32_t)(tid + i * NT2) * 16, gb + tid + i * NT2);
            cpa_commit();
        }
    }
    out[(size_t)BB * TT * II + (size_t)b * HH + myrow] = hl;
    asm volatile("cp.async.wait_group 0;" ::: "memory");
    __syncthreads();
}

// ---------------- MLP worker ----------------------------------------------------
__device__ void mlp_worker(
    const float* __restrict__ x,
    const float* __restrict__ b0, const float* __restrict__ b1,
    const float* __restrict__ b2, const float* __restrict__ b3,
    const float* __restrict__ b4, const float* __restrict__ b5,
    const float* __restrict__ b6, float* __restrict__ out,
    float* sm)
{
    __shared__ int s_blk;
    float* bufA = sm;
    float* bufB = sm + 264 * TOKP;
    const int tid = threadIdx.x;

    for (;;) {
        __syncthreads();
        if (tid == 0) s_blk = atomicAdd(&g_tick, 1);
        __syncthreads();
        const int blk = s_blk;
        if (blk >= 64 * BB) return;
        const int tc = blk >> 6;       // chunk of 64 steps
        const int b = blk & 63;        // chain
        const int need = (tc + 1) * 64;

        if (tid == 0) {
            while (ld_acquire(&g_prog[b]) < need) __nanosleep(128);
        }
        __syncthreads();

        const size_t tok0 = (size_t)b * TT + (size_t)tc * TOKN;

        for (int idx = tid; idx < TOKN * 256; idx += NT2) {
            const int tk = idx >> 8, jj = idx & 255;
            bufA[jj * TOKP + tk] = g_ht[(tok0 + tk) * HH + jj];
        }
        for (int idx = tid; idx < TOKN * 5; idx += NT2) {
            const int tk = idx / 5, i = idx - tk * 5;
            bufA[(256 + i) * TOKP + tk] = x[(tok0 + tk) * XD + II + i];
        }
        __syncthreads();

        mlp_layer<256, 261, 64, true>(bufA, bufB, g_wt + OFF0, b0); __syncthreads();
        mlp_layer<128, 256, 32, true>(bufB, bufA, g_wt + OFF1, b1); __syncthreads();
        mlp_layer< 64, 128, 16, true>(bufA, bufB, g_wt + OFF2, b2); __syncthreads();
        mlp_layer< 32,  64,  8, true>(bufB, bufA, g_wt + OFF3, b3); __syncthreads();
        mlp_layer< 16,  32,  4, true>(bufA, bufB, g_wt + OFF4, b4); __syncthreads();
        mlp_layer<  8,  16,  2, true>(bufB, bufA, g_wt + OFF5, b5); __syncthreads();

        {
            const int o = tid & 7, g0 = tid >> 3;   // g0 in [0,32)
            if (o < 7) {
                #pragma unroll
                for (int g = g0; g < TOKN; g += 32) {
                    float acc = b6[o];
                    #pragma unroll
                    for (int k = 0; k < 8; k++)
                        acc = fmaf(g_wt[OFF6 + k * 7 + o], bufA[k * TOKP + g], acc);
                    out[(tok0 + g) * II + o] = acc;
                }
            }
        }
    }
}

// ---------------- fused kernel --------------------------------------------------
__global__ __launch_bounds__(NT2, 1) void fused_kernel(
    const float* __restrict__ x, const float* __restrict__ W_hh,
    const float* __restrict__ b0, const float* __restrict__ b1,
    const float* __restrict__ b2, const float* __restrict__ b3,
    const float* __restrict__ b4, const float* __restrict__ b5,
    const float* __restrict__ b6, float* __restrict__ out)
{
    extern __shared__ float sm[];
    if (blockIdx.x < NRNN) {
        rnn_cta(W_hh, out, sm, blockIdx.x);
        // chain finished -> join the MLP pool on this SM
        mlp_worker(x, b0, b1, b2, b3, b4, b5, b6, out, sm);
    } else {
        mlp_worker(x, b0, b1, b2, b3, b4, b5, b6, out, sm);
    }
}

// ---------------- combined prep: flags + MLP weight transpose + xW --------------
__global__ void prep_xw_kernel(
    const float* __restrict__ x, const float* __restrict__ W_ih,
    const float* __restrict__ b_ih, const float* __restrict__ b_hh,
    const float* __restrict__ W0, const float* __restrict__ W1,
    const float* __restrict__ W2, const float* __restrict__ W3,
    const float* __restrict__ W4, const float* __restrict__ W5,
    const float* __restrict__ W6)
{
    if (blockIdx.x == 0) {
        if (threadIdx.x < BB) g_prog[threadIdx.x] = 0;
        if (threadIdx.x == 0) g_tick = 0;
    }
    const int stride = gridDim.x * blockDim.x;
    const int tid0 = blockIdx.x * blockDim.x + threadIdx.x;

    {
        const float* Ws[7] = {W0, W1, W2, W3, W4, W5, W6};
        const int douts[7] = {256, 128, 64, 32, 16, 8, 7};
        const int dins[7]  = {261, 256, 128, 64, 32, 16, 8};
        int off = 0;
        for (int l = 0; l < 7; l++) {
            const int dout = douts[l], din = dins[l], n = dout * din;
            const float* W = Ws[l];
            for (int idx = tid0; idx < n; idx += stride) {
                const int k = idx / dout, o = idx - k * dout;
                g_wt[off + idx] = W[o * din + k];
            }
            off += n;
        }
    }

    for (size_t idx = tid0; idx < (size_t)BB * TT * HH; idx += stride) {
        const size_t tok = idx >> 8;
        const int j = (int)(idx & 255);
        const float* xr = x + tok * XD;
        float acc = b_ih[j] + b_hh[j];
        #pragma unroll
        for (int i = 0; i < II; i++) acc = fmaf(xr[i], W_ih[j * II + i], acc);
        g_xw[idx] = acc;
    }
}

// ---------------- launch --------------------------------------------------------
extern "C" void kernel_launch(void* const* d_in, const int* in_sizes, int n_in,
                              void* d_out, int out_size)
{
    const float* x    = (const float*)d_in[0];
    const float* W_ih = (const float*)d_in[1];
    const float* W_hh = (const float*)d_in[2];
    const float* b_ih = (const float*)d_in[3];
    const float* b_hh = (const float*)d_in[4];
    const float* W[7];
    const float* bb[7];
    for (int i = 0; i < 7; i++) {
        W[i]  = (const float*)d_in[5 + 2 * i];
        bb[i] = (const float*)d_in[6 + 2 * i];
    }
    float* out = (float*)d_out;

    static int inited = 0;
    if (!inited) {
        cudaFuncSetAttribute(fused_kernel,
                             cudaFuncAttributeMaxDynamicSharedMemorySize, FUSED_SMEM_B);
        inited = 1;
    }

    prep_xw_kernel<<<512, 256>>>(x, W_ih, b_ih, b_hh,
                                 W[0], W[1], W[2], W[3], W[4], W[5], W[6]);
    fused_kernel<<<NCTA, NT2, FUSED_SMEM_B>>>(x, W_hh,
                                              bb[0], bb[1], bb[2], bb[3],
                                              bb[4], bb[5], bb[6], out);
}

// round 16
// speedup vs baseline: 1.0187x; 1.0187x over previous
#include <cuda_runtime.h>
#include <cstdint>
#include <math.h>

// Problem dims
#define BB 64
#define TT 4096
#define HH 256
#define II 7
#define XD 12   // I + F

#define NRNN 64
#define NWORK 84
#define NCTA (NRNN + NWORK)
#define NT2 256

// ---------------- device scratch ----------------------------------------------
__device__ float g_ht[(size_t)BB * TT * HH];   // RNN hidden states (256 MB)
__device__ float g_xw[(size_t)BB * TT * HH];   // precomputed xW + biases (256 MB)
__device__ float g_wt[110520];                 // transposed MLP weights
__device__ int   g_prog[BB];                   // RNN progress per chain
__device__ int   g_tick;                       // MLP chunk ticket counter

// MLP layer offsets in g_wt
#define OFF0 0
#define OFF1 66816
#define OFF2 99584
#define OFF3 107776
#define OFF4 109824
#define OFF5 110336
#define OFF6 110464

// ---------------- helpers ------------------------------------------------------
__device__ __forceinline__ unsigned long long fma2(unsigned long long a,
                                                   unsigned long long b,
                                                   unsigned long long c) {
    unsigned long long d;
    asm("fma.rn.f32x2 %0, %1, %2, %3;" : "=l"(d) : "l"(a), "l"(b), "l"(c));
    return d;
}
__device__ __forceinline__ unsigned long long pack2(float lo, float hi) {
    unsigned long long d;
    asm("mov.b64 %0, {%1, %2};" : "=l"(d) : "f"(lo), "f"(hi));
    return d;
}
__device__ __forceinline__ float2 unpack2(unsigned long long v) {
    float lo, hi;
    asm("mov.b64 {%0, %1}, %2;" : "=f"(lo), "=f"(hi) : "l"(v));
    return make_float2(lo, hi);
}
__device__ __forceinline__ int ld_acquire(const int* p) {
    int v;
    asm volatile("ld.global.acquire.gpu.b32 %0, [%1];" : "=r"(v) : "l"(p));
    return v;
}
__device__ __forceinline__ void st_release(int* p, int v) {
    asm volatile("st.global.release.gpu.b32 [%0], %1;" :: "l"(p), "r"(v));
}
__device__ __forceinline__ float fast_tanh(float x) {
    float e = __expf(2.0f * x);
    return 1.0f - __fdividef(2.0f, e + 1.0f);
}
__device__ __forceinline__ void cpa16(uint32_t s, const void* g) {
    asm volatile("cp.async.cg.shared.global [%0], [%1], 16;" :: "r"(s), "l"(g));
}
__device__ __forceinline__ void cpa_commit() {
    asm volatile("cp.async.commit_group;" ::: "memory");
}

// ---------------- RNN config ---------------------------------------------------
// 256 threads, one CTA per chain. warp w = tid>>5; lane: g = lane>>2 (k-group of
// 32 k), rr = lane&3. Thread: rows j0..j0+7 (j0 = w*32 + rr*8), k in [g*32,+32).
// Per row: 26 weight floats (13 ull, pairs 0..12) in regs, 6 (pairs 13..15) smem.
#define RKU 13        // reg ulls per row
#define WROW 8        // smem weight row stride (floats: pair13 @0, pairs14-15 @4)
#define WTST 68       // per-thread smem weight stride (64 used + 4 pad)
#define HPAD 36       // h group stride (32 used + 4 pad) -> conflict-free
#define HBUF 288      // h buffer stride (8*HPAD)
#define CH 32         // xw chunk (steps)
#define NCH (TT / CH) // 128

// smem: weights 256*68=17408 | xw 2*CH*HH=16384 | h 2*HBUF=576 => 34368 fl
#define RNN_SMF (NT2 * WTST + 2 * CH * HH + 2 * HBUF)

// ---------------- MLP config ---------------------------------------------------
#define TOKN 64
#define TOKP 68
#define MLP_SMF ((264 + 256) * TOKP)                   // 35360 fl = 141440 B
#define FUSED_SMEM_B (MLP_SMF * 4)

template<int DOUT, int DIN, int TPG, bool LEAKY>
__device__ __forceinline__ void mlp_layer(const float* __restrict__ zin,
                                          float* __restrict__ zout,
                                          const float* __restrict__ wt,
                                          const float* __restrict__ bias)
{
    const int tid = threadIdx.x;
    const int o = tid % DOUT;
    const int g = tid / DOUT;

    if constexpr (TPG >= 4) {
        constexpr int NP = TPG / 2;
        unsigned long long acc[NP];
        #pragma unroll
        for (int p = 0; p < NP; p++) acc[p] = pack2(0.0f, 0.0f);
        #pragma unroll 4
        for (int k = 0; k < DIN; k++) {
            const float w = wt[k * DOUT + o];
            const unsigned long long w2 = pack2(w, w);
            const ulonglong2* zr = (const ulonglong2*)(zin + k * TOKP + g * TPG);
            #pragma unroll
            for (int p = 0; p < TPG / 4; p++) {
                ulonglong2 u = zr[p];
                acc[2 * p]     = fma2(w2, u.x, acc[2 * p]);
                acc[2 * p + 1] = fma2(w2, u.y, acc[2 * p + 1]);
            }
        }
        const float bv = bias[o];
        float* orow = zout + o * TOKP + g * TPG;
        #pragma unroll
        for (int p = 0; p < NP; p++) {
            float2 v = unpack2(acc[p]);
            v.x += bv; v.y += bv;
            if (LEAKY) { v.x = fmaxf(v.x, 0.01f * v.x); v.y = fmaxf(v.y, 0.01f * v.y); }
            orow[2 * p] = v.x; orow[2 * p + 1] = v.y;
        }
    } else if constexpr (TPG == 2) {
        unsigned long long acc = pack2(0.0f, 0.0f);
        #pragma unroll 4
        for (int k = 0; k < DIN; k++) {
            const float w = wt[k * DOUT + o];
            unsigned long long u = *(const unsigned long long*)(zin + k * TOKP + g * 2);
            acc = fma2(pack2(w, w), u, acc);
        }
        const float bv = bias[o];
        float2 v = unpack2(acc);
        v.x += bv; v.y += bv;
        if (LEAKY) { v.x = fmaxf(v.x, 0.01f * v.x); v.y = fmaxf(v.y, 0.01f * v.y); }
        float* orow = zout + o * TOKP + g * 2;
        orow[0] = v.x; orow[1] = v.y;
    }
}

// ---------------- RNN side ------------------------------------------------------
__device__ void rnn_cta(const float* __restrict__ W_hh, float* __restrict__ out,
                        float* sm, int b)
{
    float* ws  = sm;                         // NT2*WTST
    float* xws = sm + NT2 * WTST;            // 2 x CH*HH
    float* hb  = xws + 2 * CH * HH;          // 2*HBUF
    const int tid = threadIdx.x;
    const int w = tid >> 5, lane = tid & 31;
    const int g = lane >> 2, rr = lane & 3;
    const int j0 = w * 32 + rr * 8;
    const int myrow = j0 + g;
    const int hoff = HPAD * (myrow >> 5) + (myrow & 31);
    const bool g0b = (g & 1) != 0;
    const bool g1b = (g & 2) != 0;
    const bool g2b = (g & 4) != 0;

    // register weights: 8 rows x 26 k (13 ull each, pairs 0..12)
    unsigned long long wr[8][RKU];
    #pragma unroll
    for (int r = 0; r < 8; r++) {
        const float* row = W_hh + (j0 + r) * HH + g * 32;
        const ulonglong2* src = (const ulonglong2*)row;
        #pragma unroll
        for (int i = 0; i < 6; i++) {
            ulonglong2 u = src[i];
            wr[r][2 * i] = u.x; wr[r][2 * i + 1] = u.y;
        }
        wr[r][12] = *(const unsigned long long*)(row + 24);
    }
    // smem weights: 8 rows x 6 k (pairs 13,14,15 = k_rel 26..31)
    float* wsm = ws + tid * WTST;
    #pragma unroll
    for (int r = 0; r < 8; r++) {
        const float* row = W_hh + (j0 + r) * HH + g * 32;
        *(unsigned long long*)(wsm + r * WROW) =
            *(const unsigned long long*)(row + 26);
        *(ulonglong2*)(wsm + r * WROW + 4) =
            *(const ulonglong2*)(row + 28);
    }

    for (int idx = tid; idx < 2 * HBUF; idx += NT2) hb[idx] = 0.0f;

    const float* xg = g_xw + (size_t)b * TT * HH;
    float* hout = g_ht + (size_t)b * TT * HH;
    const uint32_t xw_sbase = (uint32_t)__cvta_generic_to_shared(xws);

    // prologue: stage chunks 0 and 1 (CH*HH = 8192 fl = 2048 float4)
    #pragma unroll
    for (int i = 0; i < 8; i++)
        cpa16(xw_sbase + (uint32_t)(tid + i * NT2) * 16,
              (const float4*)xg + tid + i * NT2);
    cpa_commit();
    #pragma unroll
    for (int i = 0; i < 8; i++)
        cpa16(xw_sbase + (uint32_t)(CH * HH / 4 + tid + i * NT2) * 16,
              (const float4*)(xg + CH * HH) + tid + i * NT2);
    cpa_commit();

    int buf = 0;
    float hl = 0.0f;

    for (int c = 0; c < NCH; c++) {
        if (c >= NCH - 2) { asm volatile("cp.async.wait_group 0;" ::: "memory"); }
        else              { asm volatile("cp.async.wait_group 1;" ::: "memory"); }
        __syncthreads();
        const float* xwc = xws + (c & 1) * (CH * HH);

        for (int s = 0; s < CH; s++) {
            const float xwv = xwc[s * HH + myrow];
            const ulonglong2* h2 = (const ulonglong2*)(hb + buf * HBUF + HPAD * g);

            unsigned long long acc[8];
            #pragma unroll
            for (int r = 0; r < 8; r++) acc[r] = pack2(0.f, 0.f);

            // pairs 0..11: register weights, h consumed per-LDS
            #pragma unroll
            for (int i = 0; i < 6; i++) {
                ulonglong2 u = h2[i];
                #pragma unroll
                for (int r = 0; r < 8; r++) {
                    acc[r] = fma2(wr[r][2 * i],     u.x, acc[r]);
                    acc[r] = fma2(wr[r][2 * i + 1], u.y, acc[r]);
                }
            }
            // pairs 12 (reg) + 13 (smem)
            {
                ulonglong2 u = h2[6];
                #pragma unroll
                for (int r = 0; r < 8; r++)
                    acc[r] = fma2(wr[r][12], u.x, acc[r]);
                #pragma unroll
                for (int r = 0; r < 8; r++) {
                    unsigned long long w13 =
                        *(const unsigned long long*)(wsm + r * WROW);
                    acc[r] = fma2(w13, u.y, acc[r]);
                }
            }
            // pairs 14,15 (smem)
            {
                ulonglong2 u = h2[7];
                #pragma unroll
                for (int r = 0; r < 8; r++) {
                    ulonglong2 wv = *(const ulonglong2*)(wsm + r * WROW + 4);
                    acc[r] = fma2(wv.x, u.x, acc[r]);
                    acc[r] = fma2(wv.y, u.y, acc[r]);
                }
            }

            float p[8];
            #pragma unroll
            for (int r = 0; r < 8; r++) {
                float2 v = unpack2(acc[r]);
                p[r] = v.x + v.y;
            }

            // 3-stage reduce-scatter: lane (rr,g) ends with row j0+g.
            float q[4];
            #pragma unroll
            for (int rp = 0; rp < 4; rp++) {
                float snd = g0b ? p[2 * rp] : p[2 * rp + 1];
                float o = __shfl_xor_sync(0xFFFFFFFFu, snd, 4);
                q[rp] = (g0b ? p[2 * rp + 1] : p[2 * rp]) + o;
            }
            float u0, u1;
            {
                float snd = g1b ? q[0] : q[1];
                float o = __shfl_xor_sync(0xFFFFFFFFu, snd, 8);
                u0 = (g1b ? q[1] : q[0]) + o;
                float snd2 = g1b ? q[2] : q[3];
                float o2 = __shfl_xor_sync(0xFFFFFFFFu, snd2, 8);
                u1 = (g1b ? q[3] : q[2]) + o2;
            }
            float sd;
            {
                float snd = g2b ? u0 : u1;
                float o = __shfl_xor_sync(0xFFFFFFFFu, snd, 16);
                sd = (g2b ? u1 : u0) + o;
            }

            const float hn = fast_tanh(sd + xwv);
            hb[(buf ^ 1) * HBUF + hoff] = hn;
            hout[(size_t)(c * CH + s) * HH + myrow] = hn;
            hl = hn;
            __syncthreads();
            buf ^= 1;
        }

        if (tid == 0) st_release(&g_prog[b], (c + 1) * CH);

        if (c + 2 < NCH) {
            const float4* gb = (const float4*)(xg + (size_t)(c + 2) * CH * HH);
            const uint32_t sb = xw_sbase + (uint32_t)((c & 1) * CH * HH) * 4;
            #pragma unroll
            for (int i = 0; i < 8; i++)
                cpa16(sb + (uint32_t)(tid + i * NT2) * 16, gb + tid + i * NT2);
            cpa_commit();
        }
    }
    out[(size_t)BB * TT * II + (size_t)b * HH + myrow] = hl;
    asm volatile("cp.async.wait_group 0;" ::: "memory");
    __syncthreads();
}

// ---------------- MLP worker ----------------------------------------------------
__device__ void mlp_worker(
    const float* __restrict__ x,
    const float* __restrict__ b0, const float* __restrict__ b1,
    const float* __restrict__ b2, const float* __restrict__ b3,
    const float* __restrict__ b4, const float* __restrict__ b5,
    const float* __restrict__ b6, float* __restrict__ out,
    float* sm)
{
    __shared__ int s_blk;
    float* bufA = sm;
    float* bufB = sm + 264 * TOKP;
    const int tid = threadIdx.x;

    for (;;) {
        __syncthreads();
        if (tid == 0) s_blk = atomicAdd(&g_tick, 1);
        __syncthreads();
        const int blk = s_blk;
        if (blk >= 64 * BB) return;
        const int tc = blk >> 6;       // chunk of 64 steps
        const int b = blk & 63;        // chain
        const int need = (tc + 1) * 64;

        if (tid == 0) {
            while (ld_acquire(&g_prog[b]) < need) __nanosleep(128);
        }
        __syncthreads();

        const size_t tok0 = (size_t)b * TT + (size_t)tc * TOKN;

        for (int idx = tid; idx < TOKN * 256; idx += NT2) {
            const int tk = idx >> 8, jj = idx & 255;
            bufA[jj * TOKP + tk] = g_ht[(tok0 + tk) * HH + jj];
        }
        for (int idx = tid; idx < TOKN * 5; idx += NT2) {
            const int tk = idx / 5, i = idx - tk * 5;
            bufA[(256 + i) * TOKP + tk] = x[(tok0 + tk) * XD + II + i];
        }
        __syncthreads();

        mlp_layer<256, 261, 64, true>(bufA, bufB, g_wt + OFF0, b0); __syncthreads();
        mlp_layer<128, 256, 32, true>(bufB, bufA, g_wt + OFF1, b1); __syncthreads();
        mlp_layer< 64, 128, 16, true>(bufA, bufB, g_wt + OFF2, b2); __syncthreads();
        mlp_layer< 32,  64,  8, true>(bufB, bufA, g_wt + OFF3, b3); __syncthreads();
        mlp_layer< 16,  32,  4, true>(bufA, bufB, g_wt + OFF4, b4); __syncthreads();
        mlp_layer<  8,  16,  2, true>(bufB, bufA, g_wt + OFF5, b5); __syncthreads();

        {
            const int o = tid & 7, g0 = tid >> 3;   // g0 in [0,32)
            if (o < 7) {
                #pragma unroll
                for (int g = g0; g < TOKN; g += 32) {
                    float acc = b6[o];
                    #pragma unroll
                    for (int k = 0; k < 8; k++)
                        acc = fmaf(g_wt[OFF6 + k * 7 + o], bufA[k * TOKP + g], acc);
                    out[(tok0 + g) * II + o] = acc;
                }
            }
        }
    }
}

// ---------------- fused kernel --------------------------------------------------
__global__ __launch_bounds__(NT2, 1) void fused_kernel(
    const float* __restrict__ x, const float* __restrict__ W_hh,
    const float* __restrict__ b0, const float* __restrict__ b1,
    const float* __restrict__ b2, const float* __restrict__ b3,
    const float* __restrict__ b4, const float* __restrict__ b5,
    const float* __restrict__ b6, float* __restrict__ out)
{
    extern __shared__ float sm[];
    if (blockIdx.x < NRNN) {
        rnn_cta(W_hh, out, sm, blockIdx.x);
        // chain finished -> join the MLP pool on this SM
        mlp_worker(x, b0, b1, b2, b3, b4, b5, b6, out, sm);
    } else {
        mlp_worker(x, b0, b1, b2, b3, b4, b5, b6, out, sm);
    }
}

// ---------------- xW precompute -------------------------------------------------
__global__ void xw_kernel(const float* __restrict__ x, const float* __restrict__ W_ih,
                          const float* __restrict__ b_ih, const float* __restrict__ b_hh)
{
    const int stride = gridDim.x * blockDim.x;
    for (size_t idx = (size_t)blockIdx.x * blockDim.x + threadIdx.x;
         idx < (size_t)BB * TT * HH; idx += stride) {
        const size_t tok = idx >> 8;
        const int j = (int)(idx & 255);
        const float* xr = x + tok * XD;
        float acc = b_ih[j] + b_hh[j];
        #pragma unroll
        for (int i = 0; i < II; i++) acc = fmaf(xr[i], W_ih[j * II + i], acc);
        g_xw[idx] = acc;
    }
}

// ---------------- prep ----------------------------------------------------------
__global__ void prep_kernel(const float* __restrict__ W0, const float* __restrict__ W1,
                            const float* __restrict__ W2, const float* __restrict__ W3,
                            const float* __restrict__ W4, const float* __restrict__ W5,
                            const float* __restrict__ W6)
{
    if (blockIdx.x == 0) {
        if (threadIdx.x < BB) g_prog[threadIdx.x] = 0;
        if (threadIdx.x == 0) g_tick = 0;
    }
    const float* Ws[7] = {W0, W1, W2, W3, W4, W5, W6};
    const int douts[7] = {256, 128, 64, 32, 16, 8, 7};
    const int dins[7]  = {261, 256, 128, 64, 32, 16, 8};
    int off = 0;
    const int stride = gridDim.x * blockDim.x;
    const int tid0 = blockIdx.x * blockDim.x + threadIdx.x;
    for (int l = 0; l < 7; l++) {
        const int dout = douts[l], din = dins[l], n = dout * din;
        const float* W = Ws[l];
        for (int idx = tid0; idx < n; idx += stride) {
            const int k = idx / dout, o = idx - k * dout;
            g_wt[off + idx] = W[o * din + k];
        }
        off += n;
    }
}

// ---------------- launch --------------------------------------------------------
extern "C" void kernel_launch(void* const* d_in, const int* in_sizes, int n_in,
                              void* d_out, int out_size)
{
    const float* x    = (const float*)d_in[0];
    const float* W_ih = (const float*)d_in[1];
    const float* W_hh = (const float*)d_in[2];
    const float* b_ih = (const float*)d_in[3];
    const float* b_hh = (const float*)d_in[4];
    const float* W[7];
    const float* bb[7];
    for (int i = 0; i < 7; i++) {
        W[i]  = (const float*)d_in[5 + 2 * i];
        bb[i] = (const float*)d_in[6 + 2 * i];
    }
    float* out = (float*)d_out;

    static int inited = 0;
    if (!inited) {
        cudaFuncSetAttribute(fused_kernel,
                             cudaFuncAttributeMaxDynamicSharedMemorySize, FUSED_SMEM_B);
        inited = 1;
    }

    prep_kernel<<<64, 256>>>(W[0], W[1], W[2], W[3], W[4], W[5], W[6]);
    xw_kernel<<<512, 256>>>(x, W_ih, b_ih, b_hh);
    fused_kernel<<<NCTA, NT2, FUSED_SMEM_B>>>(x, W_hh,
                                              bb[0], bb[1], bb[2], bb[3],
                                              bb[4], bb[5], bb[6], out);
}

// round 17
// speedup vs baseline: 1.0692x; 1.0496x over previous
#include <cuda_runtime.h>
#include <cstdint>
#include <math.h>

// Problem dims
#define BB 64
#define TT 4096
#define HH 256
#define II 7
#define XD 12   // I + F

#define NRNN 64
#define NWORK 84
#define NCTA (NRNN + NWORK)
#define NT2 256

// ---------------- device scratch ----------------------------------------------
__device__ float g_ht[(size_t)BB * TT * HH];   // RNN hidden states (256 MB)
__device__ float g_xw[(size_t)BB * TT * HH];   // precomputed xW + biases (256 MB)
__device__ float g_wt[110520];                 // transposed MLP weights
__device__ int   g_prog[BB];                   // RNN progress per chain
__device__ int   g_tick;                       // MLP chunk ticket counter

// MLP layer offsets in g_wt
#define OFF0 0
#define OFF1 66816
#define OFF2 99584
#define OFF3 107776
#define OFF4 109824
#define OFF5 110336
#define OFF6 110464

// ---------------- helpers ------------------------------------------------------
__device__ __forceinline__ unsigned long long fma2(unsigned long long a,
                                                   unsigned long long b,
                                                   unsigned long long c) {
    unsigned long long d;
    asm("fma.rn.f32x2 %0, %1, %2, %3;" : "=l"(d) : "l"(a), "l"(b), "l"(c));
    return d;
}
__device__ __forceinline__ unsigned long long pack2(float lo, float hi) {
    unsigned long long d;
    asm("mov.b64 %0, {%1, %2};" : "=l"(d) : "f"(lo), "f"(hi));
    return d;
}
__device__ __forceinline__ float2 unpack2(unsigned long long v) {
    float lo, hi;
    asm("mov.b64 {%0, %1}, %2;" : "=f"(lo), "=f"(hi) : "l"(v));
    return make_float2(lo, hi);
}
__device__ __forceinline__ int ld_acquire(const int* p) {
    int v;
    asm volatile("ld.global.acquire.gpu.b32 %0, [%1];" : "=r"(v) : "l"(p));
    return v;
}
__device__ __forceinline__ void st_release(int* p, int v) {
    asm volatile("st.global.release.gpu.b32 [%0], %1;" :: "l"(p), "r"(v));
}
__device__ __forceinline__ float fast_tanh(float x) {
    float e = __expf(2.0f * x);
    return 1.0f - __fdividef(2.0f, e + 1.0f);
}
__device__ __forceinline__ void cpa16(uint32_t s, const void* g) {
    asm volatile("cp.async.cg.shared.global [%0], [%1], 16;" :: "r"(s), "l"(g));
}
__device__ __forceinline__ void cpa_commit() {
    asm volatile("cp.async.commit_group;" ::: "memory");
}

// ---------------- RNN config ---------------------------------------------------
// 256 threads, one CTA per chain. warp w = tid>>5; lane: g = lane>>2 (k-group of
// 32 k), rr = lane&3. Thread: rows j0..j0+7 (j0 = w*32 + rr*8), k in [g*32,+32).
// Per row: 26 weight floats (13 ull, pairs 0..12) in regs, 6 (pairs 13..15) smem.
#define RKU 13        // reg ulls per row
#define WROW 8        // smem weight row stride (floats: pair13 @0, pairs14-15 @4)
#define WTST 68       // per-thread smem weight stride (64 used + 4 pad)
#define HPAD 36       // h group stride (32 used + 4 pad) -> conflict-free
#define HBUF 288      // h buffer stride (8*HPAD)
#define CH 32         // xw chunk (steps)
#define NCH (TT / CH) // 128

// smem: weights 256*68=17408 | xw 2*CH*HH=16384 | h 2*HBUF=576 => 34368 fl
#define RNN_SMF (NT2 * WTST + 2 * CH * HH + 2 * HBUF)

// ---------------- MLP config ---------------------------------------------------
#define TOKN 64
#define TOKP 68
#define MLP_SMF ((264 + 256) * TOKP)                   // 35360 fl = 141440 B
#define FUSED_SMEM_B (MLP_SMF * 4)

template<int DOUT, int DIN, int TPG, bool LEAKY>
__device__ __forceinline__ void mlp_layer(const float* __restrict__ zin,
                                          float* __restrict__ zout,
                                          const float* __restrict__ wt,
                                          const float* __restrict__ bias)
{
    const int tid = threadIdx.x;
    const int o = tid % DOUT;
    const int g = tid / DOUT;

    if constexpr (TPG >= 4) {
        constexpr int NP = TPG / 2;
        unsigned long long acc[NP];
        #pragma unroll
        for (int p = 0; p < NP; p++) acc[p] = pack2(0.0f, 0.0f);
        #pragma unroll 4
        for (int k = 0; k < DIN; k++) {
            const float w = wt[k * DOUT + o];
            const unsigned long long w2 = pack2(w, w);
            const ulonglong2* zr = (const ulonglong2*)(zin + k * TOKP + g * TPG);
            #pragma unroll
            for (int p = 0; p < TPG / 4; p++) {
                ulonglong2 u = zr[p];
                acc[2 * p]     = fma2(w2, u.x, acc[2 * p]);
                acc[2 * p + 1] = fma2(w2, u.y, acc[2 * p + 1]);
            }
        }
        const float bv = bias[o];
        float* orow = zout + o * TOKP + g * TPG;
        #pragma unroll
        for (int p = 0; p < NP; p++) {
            float2 v = unpack2(acc[p]);
            v.x += bv; v.y += bv;
            if (LEAKY) { v.x = fmaxf(v.x, 0.01f * v.x); v.y = fmaxf(v.y, 0.01f * v.y); }
            orow[2 * p] = v.x; orow[2 * p + 1] = v.y;
        }
    } else if constexpr (TPG == 2) {
        unsigned long long acc = pack2(0.0f, 0.0f);
        #pragma unroll 4
        for (int k = 0; k < DIN; k++) {
            const float w = wt[k * DOUT + o];
            unsigned long long u = *(const unsigned long long*)(zin + k * TOKP + g * 2);
            acc = fma2(pack2(w, w), u, acc);
        }
        const float bv = bias[o];
        float2 v = unpack2(acc);
        v.x += bv; v.y += bv;
        if (LEAKY) { v.x = fmaxf(v.x, 0.01f * v.x); v.y = fmaxf(v.y, 0.01f * v.y); }
        float* orow = zout + o * TOKP + g * 2;
        orow[0] = v.x; orow[1] = v.y;
    }
}

// ---------------- RNN side ------------------------------------------------------
__device__ void rnn_cta(const float* __restrict__ W_hh, float* __restrict__ out,
                        float* sm, int b)
{
    float* ws  = sm;                         // NT2*WTST
    float* xws = sm + NT2 * WTST;            // 2 x CH*HH
    float* hb  = xws + 2 * CH * HH;          // 2*HBUF
    const int tid = threadIdx.x;
    const int w = tid >> 5, lane = tid & 31;
    const int g = lane >> 2, rr = lane & 3;
    const int j0 = w * 32 + rr * 8;
    const int myrow = j0 + g;
    const int hoff = HPAD * (myrow >> 5) + (myrow & 31);
    const bool g0b = (g & 1) != 0;
    const bool g1b = (g & 2) != 0;
    const bool g2b = (g & 4) != 0;

    // register weights: 8 rows x 26 k (13 ull each, pairs 0..12)
    unsigned long long wr[8][RKU];
    #pragma unroll
    for (int r = 0; r < 8; r++) {
        const float* row = W_hh + (j0 + r) * HH + g * 32;
        const ulonglong2* src = (const ulonglong2*)row;
        #pragma unroll
        for (int i = 0; i < 6; i++) {
            ulonglong2 u = src[i];
            wr[r][2 * i] = u.x; wr[r][2 * i + 1] = u.y;
        }
        wr[r][12] = *(const unsigned long long*)(row + 24);
    }
    // smem weights: 8 rows x 6 k (pairs 13,14,15 = k_rel 26..31)
    float* wsm = ws + tid * WTST;
    #pragma unroll
    for (int r = 0; r < 8; r++) {
        const float* row = W_hh + (j0 + r) * HH + g * 32;
        *(unsigned long long*)(wsm + r * WROW) =
            *(const unsigned long long*)(row + 26);
        *(ulonglong2*)(wsm + r * WROW + 4) =
            *(const ulonglong2*)(row + 28);
    }

    for (int idx = tid; idx < 2 * HBUF; idx += NT2) hb[idx] = 0.0f;

    const float* xg = g_xw + (size_t)b * TT * HH;
    float* hout = g_ht + (size_t)b * TT * HH;
    const uint32_t xw_sbase = (uint32_t)__cvta_generic_to_shared(xws);

    // prologue: stage chunks 0 and 1 (CH*HH = 8192 fl = 2048 float4)
    #pragma unroll
    for (int i = 0; i < 8; i++)
        cpa16(xw_sbase + (uint32_t)(tid + i * NT2) * 16,
              (const float4*)xg + tid + i * NT2);
    cpa_commit();
    #pragma unroll
    for (int i = 0; i < 8; i++)
        cpa16(xw_sbase + (uint32_t)(CH * HH / 4 + tid + i * NT2) * 16,
              (const float4*)(xg + CH * HH) + tid + i * NT2);
    cpa_commit();

    int buf = 0;
    float hl = 0.0f;

    for (int c = 0; c < NCH; c++) {
        if (c >= NCH - 2) { asm volatile("cp.async.wait_group 0;" ::: "memory"); }
        else              { asm volatile("cp.async.wait_group 1;" ::: "memory"); }
        __syncthreads();
        const float* xwc = xws + (c & 1) * (CH * HH);

        for (int s = 0; s < CH; s++) {
            const float xwv = xwc[s * HH + myrow];
            const ulonglong2* h2 = (const ulonglong2*)(hb + buf * HBUF + HPAD * g);

            unsigned long long acc[8];
            #pragma unroll
            for (int r = 0; r < 8; r++) acc[r] = pack2(0.f, 0.f);

            // pairs 0..11: register weights, h consumed per-LDS
            #pragma unroll
            for (int i = 0; i < 6; i++) {
                ulonglong2 u = h2[i];
                #pragma unroll
                for (int r = 0; r < 8; r++) {
                    acc[r] = fma2(wr[r][2 * i],     u.x, acc[r]);
                    acc[r] = fma2(wr[r][2 * i + 1], u.y, acc[r]);
                }
            }
            // pairs 12 (reg) + 13 (smem)
            {
                ulonglong2 u = h2[6];
                #pragma unroll
                for (int r = 0; r < 8; r++)
                    acc[r] = fma2(wr[r][12], u.x, acc[r]);
                #pragma unroll
                for (int r = 0; r < 8; r++) {
                    unsigned long long w13 =
                        *(const unsigned long long*)(wsm + r * WROW);
                    acc[r] = fma2(w13, u.y, acc[r]);
                }
            }
            // pairs 14,15 (smem)
            {
                ulonglong2 u = h2[7];
                #pragma unroll
                for (int r = 0; r < 8; r++) {
                    ulonglong2 wv = *(const ulonglong2*)(wsm + r * WROW + 4);
                    acc[r] = fma2(wv.x, u.x, acc[r]);
                    acc[r] = fma2(wv.y, u.y, acc[r]);
                }
            }

            float p[8];
            #pragma unroll
            for (int r = 0; r < 8; r++) {
                float2 v = unpack2(acc[r]);
                p[r] = v.x + v.y;
            }

            // 3-stage reduce-scatter: lane (rr,g) ends with row j0+g.
            float q[4];
            #pragma unroll
            for (int rp = 0; rp < 4; rp++) {
                float snd = g0b ? p[2 * rp] : p[2 * rp + 1];
                float o = __shfl_xor_sync(0xFFFFFFFFu, snd, 4);
                q[rp] = (g0b ? p[2 * rp + 1] : p[2 * rp]) + o;
            }
            float u0, u1;
            {
                float snd = g1b ? q[0] : q[1];
                float o = __shfl_xor_sync(0xFFFFFFFFu, snd, 8);
                u0 = (g1b ? q[1] : q[0]) + o;
                float snd2 = g1b ? q[2] : q[3];
                float o2 = __shfl_xor_sync(0xFFFFFFFFu, snd2, 8);
                u1 = (g1b ? q[3] : q[2]) + o2;
            }
            float sd;
            {
                float snd = g2b ? u0 : u1;
                float o = __shfl_xor_sync(0xFFFFFFFFu, snd, 16);
                sd = (g2b ? u1 : u0) + o;
            }

            const float hn = fast_tanh(sd + xwv);
            hb[(buf ^ 1) * HBUF + hoff] = hn;
            hout[(size_t)(c * CH + s) * HH + myrow] = hn;
            hl = hn;
            __syncthreads();
            buf ^= 1;
        }

        if (tid == 0) st_release(&g_prog[b], (c + 1) * CH);

        if (c + 2 < NCH) {
            const float4* gb = (const float4*)(xg + (size_t)(c + 2) * CH * HH);
            const uint32_t sb = xw_sbase + (uint32_t)((c & 1) * CH * HH) * 4;
            #pragma unroll
            for (int i = 0; i < 8; i++)
                cpa16(sb + (uint32_t)(tid + i * NT2) * 16, gb + tid + i * NT2);
            cpa_commit();
        }
    }
    out[(size_t)BB * TT * II + (size_t)b * HH + myrow] = hl;
    asm volatile("cp.async.wait_group 0;" ::: "memory");
    __syncthreads();
}

// ---------------- MLP worker ----------------------------------------------------
__device__ void mlp_worker(
    const float* __restrict__ x,
    const float* __restrict__ b0, const float* __restrict__ b1,
    const float* __restrict__ b2, const float* __restrict__ b3,
    const float* __restrict__ b4, const float* __restrict__ b5,
    const float* __restrict__ b6, float* __restrict__ out,
    float* sm)
{
    __shared__ int s_blk;
    float* bufA = sm;
    float* bufB = sm + 264 * TOKP;
    const int tid = threadIdx.x;

    for (;;) {
        __syncthreads();
        if (tid == 0) s_blk = atomicAdd(&g_tick, 1);
        __syncthreads();
        const int blk = s_blk;
        if (blk >= 64 * BB) return;
        const int tc = blk >> 6;       // chunk of 64 steps
        const int b = blk & 63;        // chain
        const int need = (tc + 1) * 64;

        if (tid == 0) {
            while (ld_acquire(&g_prog[b]) < need) __nanosleep(128);
        }
        __syncthreads();

        const size_t tok0 = (size_t)b * TT + (size_t)tc * TOKN;

        for (int idx = tid; idx < TOKN * 256; idx += NT2) {
            const int tk = idx >> 8, jj = idx & 255;
            bufA[jj * TOKP + tk] = g_ht[(tok0 + tk) * HH + jj];
        }
        for (int idx = tid; idx < TOKN * 5; idx += NT2) {
            const int tk = idx / 5, i = idx - tk * 5;
            bufA[(256 + i) * TOKP + tk] = x[(tok0 + tk) * XD + II + i];
        }
        __syncthreads();

        mlp_layer<256, 261, 64, true>(bufA, bufB, g_wt + OFF0, b0); __syncthreads();
        mlp_layer<128, 256, 32, true>(bufB, bufA, g_wt + OFF1, b1); __syncthreads();
        mlp_layer< 64, 128, 16, true>(bufA, bufB, g_wt + OFF2, b2); __syncthreads();
        mlp_layer< 32,  64,  8, true>(bufB, bufA, g_wt + OFF3, b3); __syncthreads();
        mlp_layer< 16,  32,  4, true>(bufA, bufB, g_wt + OFF4, b4); __syncthreads();
        mlp_layer<  8,  16,  2, true>(bufB, bufA, g_wt + OFF5, b5); __syncthreads();

        {
            const int o = tid & 7, g0 = tid >> 3;   // g0 in [0,32)
            if (o < 7) {
                #pragma unroll
                for (int g = g0; g < TOKN; g += 32) {
                    float acc = b6[o];
                    #pragma unroll
                    for (int k = 0; k < 8; k++)
                        acc = fmaf(g_wt[OFF6 + k * 7 + o], bufA[k * TOKP + g], acc);
                    out[(tok0 + g) * II + o] = acc;
                }
            }
        }
    }
}

// ---------------- fused kernel --------------------------------------------------
__global__ __launch_bounds__(NT2, 1) void fused_kernel(
    const float* __restrict__ x, const float* __restrict__ W_hh,
    const float* __restrict__ b0, const float* __restrict__ b1,
    const float* __restrict__ b2, const float* __restrict__ b3,
    const float* __restrict__ b4, const float* __restrict__ b5,
    const float* __restrict__ b6, float* __restrict__ out)
{
    extern __shared__ float sm[];
    if (blockIdx.x < NRNN) {
        rnn_cta(W_hh, out, sm, blockIdx.x);
        // chain finished -> join the MLP pool on this SM
        mlp_worker(x, b0, b1, b2, b3, b4, b5, b6, out, sm);
    } else {
        mlp_worker(x, b0, b1, b2, b3, b4, b5, b6, out, sm);
    }
}

// ---------------- combined prep: flags + MLP weight transpose + xW --------------
__global__ void prep_xw_kernel(
    const float* __restrict__ x, const float* __restrict__ W_ih,
    const float* __restrict__ b_ih, const float* __restrict__ b_hh,
    const float* __restrict__ W0, const float* __restrict__ W1,
    const float* __restrict__ W2, const float* __restrict__ W3,
    const float* __restrict__ W4, const float* __restrict__ W5,
    const float* __restrict__ W6)
{
    if (blockIdx.x == 0) {
        if (threadIdx.x < BB) g_prog[threadIdx.x] = 0;
        if (threadIdx.x == 0) g_tick = 0;
    }
    const int stride = gridDim.x * blockDim.x;
    const int tid0 = blockIdx.x * blockDim.x + threadIdx.x;

    {
        const float* Ws[7] = {W0, W1, W2, W3, W4, W5, W6};
        const int douts[7] = {256, 128, 64, 32, 16, 8, 7};
        const int dins[7]  = {261, 256, 128, 64, 32, 16, 8};
        int off = 0;
        for (int l = 0; l < 7; l++) {
            const int dout = douts[l], din = dins[l], n = dout * din;
            const float* W = Ws[l];
            for (int idx = tid0; idx < n; idx += stride) {
                const int k = idx / dout, o = idx - k * dout;
                g_wt[off + idx] = W[o * din + k];
            }
            off += n;
        }
    }

    for (size_t idx = tid0; idx < (size_t)BB * TT * HH; idx += stride) {
        const size_t tok = idx >> 8;
        const int j = (int)(idx & 255);
        const float* xr = x + tok * XD;
        float acc = b_ih[j] + b_hh[j];
        #pragma unroll
        for (int i = 0; i < II; i++) acc = fmaf(xr[i], W_ih[j * II + i], acc);
        g_xw[idx] = acc;
    }
}

// ---------------- launch --------------------------------------------------------
extern "C" void kernel_launch(void* const* d_in, const int* in_sizes, int n_in,
                              void* d_out, int out_size)
{
    const float* x    = (const float*)d_in[0];
    const float* W_ih = (const float*)d_in[1];
    const float* W_hh = (const float*)d_in[2];
    const float* b_ih = (const float*)d_in[3];
    const float* b_hh = (const float*)d_in[4];
    const float* W[7];
    const float* bb[7];
    for (int i = 0; i < 7; i++) {
        W[i]  = (const float*)d_in[5 + 2 * i];
        bb[i] = (const float*)d_in[6 + 2 * i];
    }
    float* out = (float*)d_out;

    static int inited = 0;
    if (!inited) {
        cudaFuncSetAttribute(fused_kernel,
                             cudaFuncAttributeMaxDynamicSharedMemorySize, FUSED_SMEM_B);
        inited = 1;
    }

    prep_xw_kernel<<<512, 256>>>(x, W_ih, b_ih, b_hh,
                                 W[0], W[1], W[2], W[3], W[4], W[5], W[6]);
    fused_kernel<<<NCTA, NT2, FUSED_SMEM_B>>>(x, W_hh,
                                              bb[0], bb[1], bb[2], bb[3],
                                              bb[4], bb[5], bb[6], out);
}